// round 15
// baseline (speedup 1.0000x reference)
#include <cuda_runtime.h>

#define NN  192
#define NN2 (NN*NN)
#define NN3 (NN*NN*NN)

#define INV2DX     96.0f          // 1/(2*dx), dx = 1/N
#define MU_REF_F   1.8e-5f
#define CP_OVER_PR 1395.833333f   // 1005 / 0.72

#define TX 32
#define TY 8
#define CHUNK 64
#define PX  (TX + 2)              // 34 flux-plane x extent
#define PY  (TY + 2)              // 10 flux-plane y extent
#define PX2 (TX + 4)              // 36 u/T staging x extent
#define PY2 (TY + 4)              // 12 u/T staging y extent
#define NSTG (PX2 * PY2)          // 432
#define NRING (NSTG - TX * TY)    // 176 non-center staging points
#define NTHREADS (TX * TY)        // 256

__device__ __forceinline__ int wrapg(int i) { return (i < 0) ? i + NN : ((i >= NN) ? i - NN : i); }
__device__ __forceinline__ int slot4(int p) { return (p + 4) & 3; }

__device__ __forceinline__ float4 f4diff(float4 a, float4 b) {
    return make_float4((a.x - b.x) * INV2DX, (a.y - b.y) * INV2DX,
                       (a.z - b.z) * INV2DX, (a.w - b.w) * INV2DX);
}

// c = {u0,u1,u2,T}; fz = {t00,t01,t02,E0}, xq = {t02,t12,t22,E2}, yq = {t01,t11,t12,E1}
__device__ __forceinline__ void flux_math4(const float4 c, const float4 gz,
                                           const float4 gy, const float4 gx,
                                           float4& fz, float4& xq, float4& yq)
{
    const float divu = gz.x + gy.y + gx.z;
    const float mu   = MU_REF_F * __powf(c.w, 0.7f);
    const float kk   = mu * CP_OVER_PR;
    const float lam  = -(2.0f / 3.0f) * mu * divu;

    const float t00 = 2.0f * mu * gz.x + lam;
    const float t11 = 2.0f * mu * gy.y + lam;
    const float t22 = 2.0f * mu * gx.z + lam;
    const float t01 = mu * (gy.x + gz.y);
    const float t02 = mu * (gx.x + gz.z);
    const float t12 = mu * (gx.y + gy.z);

    const float E0 = kk * gz.w + c.x * t00 + c.y * t01 + c.z * t02;
    const float E1 = kk * gy.w + c.x * t01 + c.y * t11 + c.z * t12;
    const float E2 = kk * gx.w + c.x * t02 + c.y * t12 + c.z * t22;

    fz = make_float4(t00, t01, t02, E0);
    xq = make_float4(t02, t12, t22, E2);
    yq = make_float4(t01, t11, t12, E1);
}

__global__ void __launch_bounds__(NTHREADS)
fused13(const float* __restrict__ u, const float* __restrict__ T, float* __restrict__ out)
{
    __shared__ float4 sU[4][NSTG];        // 4 rotating u/T plane slots, AoS (27.6 KB)
    __shared__ float4 sFy[2][PY][TX];     // y-flux comps {t01,t11,t12,E1}  (10.2 KB)
    __shared__ float4 sFx[2][TY][2];      // x-flux comps at edge cols       (0.5 KB)

    const int tid = threadIdx.y * TX + threadIdx.x;
    const int tx = threadIdx.x, ty = threadIdx.y;
    const int x0 = blockIdx.x * TX;
    const int y0 = blockIdx.y * TY;
    const int z0 = blockIdx.z * CHUNK;

    const int gx_ = x0 + tx, gy_ = y0 + ty;

    // ---- center fill coords; staging job0 = OWN center column ----
    const int cfy = ty + 1;                            // flux row 1..8
    const int uoffc = (cfy + 1) * PX2 + (tx + 2);      // AoS point index
    const int sgb0  = gy_ * NN + gx_;                  // own column

    // ---- staging job1: the 176 ring points, tid < 176 ----
    const bool hasq1 = (tid < NRING);
    int sgb1 = 0, suo1 = 0;
    {
        int row, col;
        if (tid < 144) {                 // 4 full rows: 0,1,10,11
            const int r = tid / PX2;
            row = (r < 2) ? r : r + 8;
            col = tid - r * PX2;
        } else {                         // rows 2..9, cols {0,1,34,35}
            const int k = (tid < NRING) ? (tid - 144) : 0;
            row = 2 + (k >> 2);
            col = (k & 2) ? (34 + (k & 1)) : (k & 1);
        }
        sgb1 = wrapg(y0 + row - 2) * NN + wrapg(x0 + col - 2);
        suo1 = row * PX2 + col;
    }

    // ---- halo job decode (tid < 80): 64 y-halo (warps 0,1) + 16 x-halo ----
    const bool isY = (tid < 64);
    const bool isH = (tid < 80);
    int uoffh = 0, hy_r = 0, hy_c = 0, hx_r = 0, hx_s = 0;
    {
        if (isY) {
            const int hfy = (tid >= 32) ? (PY - 1) : 0;   // flux rows 0 / 9
            const int hfx = 1 + (tid & 31);               // flux cols 1..32, lane-consecutive
            uoffh = (hfy + 1) * PX2 + (hfx + 1);
            hy_r = hfy; hy_c = hfx - 1;
        } else if (isH) {
            const int r = tid - 64;
            hx_s = r >> 3;                                // 0: fx=0, 1: fx=33
            hx_r = r & 7;
            const int hfx = hx_s ? (PX - 1) : 0;
            uoffh = (hx_r + 2) * PX2 + (hfx + 1);
        }
    }

    float4 pr0, pr1;                    // prefetch registers (own col, ring)
    float4 vm, vc;                      // u/T register z-pipeline (own column)
    float4 hm, hc;                      // halo-column register z-pipeline
    float4 fzm, fzc, fzp;               // {t00,t01,t02,E0} pipeline
    float4 xq_c, xq_n;                  // {t02,t12,t22,E2} at plane z / z+1

    auto ld_plane = [&](int p, float4& a, float4& b) {
        const int zo = wrapg(p) * NN2;
        a.x = u[0 * NN3 + zo + sgb0];
        a.y = u[1 * NN3 + zo + sgb0];
        a.z = u[2 * NN3 + zo + sgb0];
        a.w = T[zo + sgb0];
        if (hasq1) {
            b.x = u[0 * NN3 + zo + sgb1];
            b.y = u[1 * NN3 + zo + sgb1];
            b.z = u[2 * NN3 + zo + sgb1];
            b.w = T[zo + sgb1];
        }
    };
    auto commit = [&](int slot, const float4 a, const float4 b) {
        sU[slot][uoffc] = a;
        if (hasq1) sU[slot][suo1] = b;
    };

    // center flux fill for plane p: Uc = slot of p; vmL=v(p-1), vcL=v(p), vpv=v(p+1).
    auto fill_center = [&](const float4* Uc, const float4 vmL, const float4 vcL,
                           const float4 vpv, float4& fz_o, float4& xq_o,
                           int s1, bool storeY) {
        const float4 gz  = f4diff(vpv, vmL);
        const float4 gy  = f4diff(Uc[uoffc + PX2], Uc[uoffc - PX2]);
        float4 xl, xr;
        xl.x = __shfl_up_sync(0xffffffffu, vcL.x, 1);
        xl.y = __shfl_up_sync(0xffffffffu, vcL.y, 1);
        xl.z = __shfl_up_sync(0xffffffffu, vcL.z, 1);
        xl.w = __shfl_up_sync(0xffffffffu, vcL.w, 1);
        xr.x = __shfl_down_sync(0xffffffffu, vcL.x, 1);
        xr.y = __shfl_down_sync(0xffffffffu, vcL.y, 1);
        xr.z = __shfl_down_sync(0xffffffffu, vcL.z, 1);
        xr.w = __shfl_down_sync(0xffffffffu, vcL.w, 1);
        if (tx == 0)  xl = Uc[uoffc - 1];
        if (tx == 31) xr = Uc[uoffc + 1];
        const float4 gx = f4diff(xr, xl);
        float4 yq;
        flux_math4(vcL, gz, gy, gx, fz_o, xq_o, yq);
        if (storeY) sFy[s1][cfy][tx] = yq;
    };

    // halo flux fill for plane p: Uc = slot of p, hp = v_h(p+1) pre-loaded.
    // y-halo warps (0,1): gx via shfl of the register column (lane edges patched).
    auto fill_halo = [&](const float4* Uc, const float4 hp, int s1) {
        const float4 gz = f4diff(hp, hm);
        const float4 gy = f4diff(Uc[uoffh + PX2], Uc[uoffh - PX2]);
        float4 gx;
        if (isY) {
            float4 xl, xr;
            xl.x = __shfl_up_sync(0xffffffffu, hc.x, 1);
            xl.y = __shfl_up_sync(0xffffffffu, hc.y, 1);
            xl.z = __shfl_up_sync(0xffffffffu, hc.z, 1);
            xl.w = __shfl_up_sync(0xffffffffu, hc.w, 1);
            xr.x = __shfl_down_sync(0xffffffffu, hc.x, 1);
            xr.y = __shfl_down_sync(0xffffffffu, hc.y, 1);
            xr.z = __shfl_down_sync(0xffffffffu, hc.z, 1);
            xr.w = __shfl_down_sync(0xffffffffu, hc.w, 1);
            const int lane = tid & 31;
            if (lane == 0)  xl = Uc[uoffh - 1];
            if (lane == 31) xr = Uc[uoffh + 1];
            gx = f4diff(xr, xl);
        } else {
            gx = f4diff(Uc[uoffh + 1], Uc[uoffh - 1]);
        }
        float4 hfz, hxq, hyq;
        flux_math4(hc, gz, gy, gx, hfz, hxq, hyq);
        if (isY) sFy[s1][hy_r][hy_c] = hyq;
        else     sFx[s1][hx_r][hx_s] = hxq;
        hm = hc; hc = hp;
    };

    // ============================ prologue ============================
    {
        float4 a, b;
        ld_plane(z0 - 2, a, b); commit(slot4(z0 - 2), a, b); vm = a;
        ld_plane(z0 - 1, a, b); commit(slot4(z0 - 1), a, b); vc = a;
        ld_plane(z0,     a, b); commit(slot4(z0),     a, b);
        const float4 v_z0 = a;
        __syncthreads();

        if (isH) {
            hm = sU[slot4(z0 - 1)][uoffh];
            hc = sU[slot4(z0)][uoffh];
        }

        ld_plane(z0 + 1, pr0, pr1);
        // fill plane z0-1: center only (its y/x comps never read)
        float4 xq_d;
        fill_center(sU[slot4(z0 - 1)], vm, vc, v_z0, fzm, xq_d, 0, false);
        vm = vc; vc = v_z0;
        commit(slot4(z0 + 1), pr0, pr1);   // slot disjoint from live reads
        const float4 vnext1 = pr0;          // v(z0+1)
        __syncthreads();

        ld_plane(z0 + 2, pr0, pr1);
        // fill plane z0: full
        fill_center(sU[slot4(z0)], vm, vc, vnext1, fzc, xq_c, z0 & 1, true);
        if (isH) {
            const float4 hp = sU[slot4(z0 + 1)][uoffh];
            fill_halo(sU[slot4(z0)], hp, z0 & 1);
        }
        vm = vc; vc = vnext1;
    }

    // ============================ main loop ============================
    for (int zi = 0; zi < CHUNK; zi++) {
        const int z = z0 + zi;

        // 1. commit prefetched plane z+2 (slot disjoint from laggard reads)
        commit(slot4(z + 2), pr0, pr1);
        const float4 vnext = pr0;           // v(z+2), own column
        __syncthreads();

        // 2. prefetch plane z+3
        if (zi + 1 < CHUNK) ld_plane(z + 3, pr0, pr1);

        // 3. fill flux plane z+1 (gz from registers; gy/gx from smem+shfl)
        fill_center(sU[slot4(z + 1)], vm, vc, vnext, fzp, xq_n, (z + 1) & 1, true);
        if (isH) {
            const float4 hp = sU[slot4(z + 2)][uoffh];
            fill_halo(sU[slot4(z + 1)], hp, (z + 1) & 1);
        }

        // 4. output plane z
        {
            const int s = z & 1;
            const float4 yp = sFy[s][cfy + 1][tx];
            const float4 ym = sFy[s][cfy - 1][tx];
            float4 xl, xr;
            xl.x = __shfl_up_sync(0xffffffffu, xq_c.x, 1);
            xl.y = __shfl_up_sync(0xffffffffu, xq_c.y, 1);
            xl.z = __shfl_up_sync(0xffffffffu, xq_c.z, 1);
            xl.w = __shfl_up_sync(0xffffffffu, xq_c.w, 1);
            xr.x = __shfl_down_sync(0xffffffffu, xq_c.x, 1);
            xr.y = __shfl_down_sync(0xffffffffu, xq_c.y, 1);
            xr.z = __shfl_down_sync(0xffffffffu, xq_c.z, 1);
            xr.w = __shfl_down_sync(0xffffffffu, xq_c.w, 1);
            if (tx == 0)  xl = sFx[s][ty][0];
            if (tx == 31) xr = sFx[s][ty][1];

            const float mom0 = (fzp.x - fzm.x) + (yp.x - ym.x) + (xr.x - xl.x);
            const float mom1 = (fzp.y - fzm.y) + (yp.y - ym.y) + (xr.y - xl.y);
            const float mom2 = (fzp.z - fzm.z) + (yp.z - ym.z) + (xr.z - xl.z);
            const float en   = (fzp.w - fzm.w) + (yp.w - ym.w) + (xr.w - xl.w);

            const int idx = z * NN2 + gy_ * NN + gx_;
            out[0 * NN3 + idx] = 0.0f;
            out[1 * NN3 + idx] = mom0 * INV2DX;
            out[2 * NN3 + idx] = mom1 * INV2DX;
            out[3 * NN3 + idx] = mom2 * INV2DX;
            out[4 * NN3 + idx] = en * INV2DX;
        }

        // 5. rotate pipelines
        fzm = fzc; fzc = fzp;
        xq_c = xq_n;
        vm = vc; vc = vnext;
    }
}

extern "C" void kernel_launch(void* const* d_in, const int* in_sizes, int n_in,
                              void* d_out, int out_size)
{
    const float* u = (const float*)d_in[0];   // [3, N, N, N]
    const float* T = (const float*)d_in[1];   // [N, N, N]
    float* out = (float*)d_out;               // [5, N, N, N]

    dim3 grid(NN / TX, NN / TY, NN / CHUNK);  // 6 x 24 x 3 = 432 blocks
    dim3 block(TX, TY, 1);
    fused13<<<grid, block>>>(u, T, out);
}

// round 16
// speedup vs baseline: 1.1522x; 1.1522x over previous
#include <cuda_runtime.h>

#define NN  192
#define NN2 (NN*NN)
#define NN3 (NN*NN*NN)

#define INV2DX     96.0f          // 1/(2*dx), dx = 1/N
#define MU_REF_F   1.8e-5f
#define CP_OVER_PR 1395.833333f   // 1005 / 0.72

#define TX 32
#define TY 8
#define CHUNK 64
#define PX  (TX + 2)              // 34 flux-plane x extent
#define PY  (TY + 2)              // 10 flux-plane y extent
#define PX2 (TX + 4)              // 36 u/T staging x extent
#define PY2 (TY + 4)              // 12 u/T staging y extent
#define NSTG (PX2 * PY2)          // 432
#define NRING (NSTG - TX * TY)    // 176 non-center staging points
#define NTHREADS (TX * TY)        // 256

__device__ __forceinline__ int wrapg(int i) { return (i < 0) ? i + NN : ((i >= NN) ? i - NN : i); }
__device__ __forceinline__ int slot4(int p) { return (p + 4) & 3; }

__device__ __forceinline__ float4 f4diff(float4 a, float4 b) {
    return make_float4((a.x - b.x) * INV2DX, (a.y - b.y) * INV2DX,
                       (a.z - b.z) * INV2DX, (a.w - b.w) * INV2DX);
}

// c = {u0,u1,u2,T}; fz = {t00,t01,t02,E0}, xq = {t02,t12,t22,E2}, yq = {t01,t11,t12,E1}
__device__ __forceinline__ void flux_math4(const float4 c, const float4 gz,
                                           const float4 gy, const float4 gx,
                                           float4& fz, float4& xq, float4& yq)
{
    const float divu = gz.x + gy.y + gx.z;
    const float mu   = MU_REF_F * __powf(c.w, 0.7f);
    const float kk   = mu * CP_OVER_PR;
    const float lam  = -(2.0f / 3.0f) * mu * divu;

    const float t00 = 2.0f * mu * gz.x + lam;
    const float t11 = 2.0f * mu * gy.y + lam;
    const float t22 = 2.0f * mu * gx.z + lam;
    const float t01 = mu * (gy.x + gz.y);
    const float t02 = mu * (gx.x + gz.z);
    const float t12 = mu * (gx.y + gy.z);

    const float E0 = kk * gz.w + c.x * t00 + c.y * t01 + c.z * t02;
    const float E1 = kk * gy.w + c.x * t01 + c.y * t11 + c.z * t12;
    const float E2 = kk * gx.w + c.x * t02 + c.y * t12 + c.z * t22;

    fz = make_float4(t00, t01, t02, E0);
    xq = make_float4(t02, t12, t22, E2);
    yq = make_float4(t01, t11, t12, E1);
}

__global__ void __launch_bounds__(NTHREADS)
fused8(const float* __restrict__ u, const float* __restrict__ T, float* __restrict__ out)
{
    __shared__ float4 sU[4][NSTG];        // 4 rotating u/T plane slots, AoS (27.6 KB)
    __shared__ float4 sFy[2][PY][TX];     // y-flux comps {t01,t11,t12,E1}  (10.2 KB)
    __shared__ float4 sFx[2][TY][2];      // x-flux comps at edge cols       (0.5 KB)

    const int tid = threadIdx.y * TX + threadIdx.x;
    const int tx = threadIdx.x, ty = threadIdx.y;
    const int x0 = blockIdx.x * TX;
    const int y0 = blockIdx.y * TY;
    const int z0 = blockIdx.z * CHUNK;

    const int gx_ = x0 + tx, gy_ = y0 + ty;

    // ---- center fill coords; staging job0 = OWN center column ----
    const int cfy = ty + 1;                            // flux row 1..8
    const int uoffc = (cfy + 1) * PX2 + (tx + 2);      // AoS point index
    const int sgb0  = gy_ * NN + gx_;                  // own column

    // ---- staging job1: the 176 ring points, tid < 176 ----
    const bool hasq1 = (tid < NRING);
    int sgb1 = 0, suo1 = 0;
    {
        int row, col;
        if (tid < 144) {                 // 4 full rows: 0,1,10,11
            const int r = tid / PX2;
            row = (r < 2) ? r : r + 8;
            col = tid - r * PX2;
        } else {                         // rows 2..9, cols {0,1,34,35}
            const int k = (tid < NRING) ? (tid - 144) : 0;
            row = 2 + (k >> 2);
            col = (k & 2) ? (34 + (k & 1)) : (k & 1);
        }
        sgb1 = wrapg(y0 + row - 2) * NN + wrapg(x0 + col - 2);
        suo1 = row * PX2 + col;
    }

    // ---- halo job decode (tid < 80): 64 y-halo + 16 x-halo ----
    const bool isY = (tid < 64);
    const bool isH = (tid < 80);
    int uoffh = 0, hy_r = 0, hy_c = 0, hx_r = 0, hx_s = 0;
    {
        if (isY) {
            const int hfy = (tid >= 32) ? (PY - 1) : 0;   // flux rows 0 / 9
            const int hfx = 1 + (tid & 31);               // flux cols 1..32
            uoffh = (hfy + 1) * PX2 + (hfx + 1);
            hy_r = hfy; hy_c = hfx - 1;
        } else if (isH) {
            const int r = tid - 64;
            hx_s = r >> 3;                                // 0: fx=0, 1: fx=33
            hx_r = r & 7;
            const int hfx = hx_s ? (PX - 1) : 0;
            uoffh = (hx_r + 2) * PX2 + (hfx + 1);
        }
    }

    float4 pr0, pr1;                    // prefetch registers (own col, ring)
    float4 vm, vc;                      // u/T register z-pipeline (own column)
    float4 hm, hc;                      // halo-column register z-pipeline
    float4 fzm, fzc, fzp;               // {t00,t01,t02,E0} pipeline
    float4 xq_c, xq_n;                  // {t02,t12,t22,E2} at plane z / z+1

    auto ld_plane = [&](int p, float4& a, float4& b) {
        const int zo = wrapg(p) * NN2;
        a.x = u[0 * NN3 + zo + sgb0];
        a.y = u[1 * NN3 + zo + sgb0];
        a.z = u[2 * NN3 + zo + sgb0];
        a.w = T[zo + sgb0];
        if (hasq1) {
            b.x = u[0 * NN3 + zo + sgb1];
            b.y = u[1 * NN3 + zo + sgb1];
            b.z = u[2 * NN3 + zo + sgb1];
            b.w = T[zo + sgb1];
        }
    };
    auto commit = [&](int slot, const float4 a, const float4 b) {
        sU[slot][uoffc] = a;
        if (hasq1) sU[slot][suo1] = b;
    };

    // center flux fill for plane p: Uc = slot of p; vmL=v(p-1), vcL=v(p), vpv=v(p+1).
    auto fill_center = [&](const float4* Uc, const float4 vmL, const float4 vcL,
                           const float4 vpv, float4& fz_o, float4& xq_o,
                           int s1, bool storeY) {
        const float4 gz  = f4diff(vpv, vmL);
        const float4 gy  = f4diff(Uc[uoffc + PX2], Uc[uoffc - PX2]);
        float4 xl, xr;
        xl.x = __shfl_up_sync(0xffffffffu, vcL.x, 1);
        xl.y = __shfl_up_sync(0xffffffffu, vcL.y, 1);
        xl.z = __shfl_up_sync(0xffffffffu, vcL.z, 1);
        xl.w = __shfl_up_sync(0xffffffffu, vcL.w, 1);
        xr.x = __shfl_down_sync(0xffffffffu, vcL.x, 1);
        xr.y = __shfl_down_sync(0xffffffffu, vcL.y, 1);
        xr.z = __shfl_down_sync(0xffffffffu, vcL.z, 1);
        xr.w = __shfl_down_sync(0xffffffffu, vcL.w, 1);
        if (tx == 0)  xl = Uc[uoffc - 1];
        if (tx == 31) xr = Uc[uoffc + 1];
        const float4 gx = f4diff(xr, xl);
        float4 yq;
        flux_math4(vcL, gz, gy, gx, fz_o, xq_o, yq);
        if (storeY) sFy[s1][cfy][tx] = yq;
    };

    // halo flux fill for plane p: Uc = slot of p, hp = v_h(p+1) pre-loaded.
    auto fill_halo = [&](const float4* Uc, const float4 hp, int s1) {
        const float4 gz = f4diff(hp, hm);
        const float4 gy = f4diff(Uc[uoffh + PX2], Uc[uoffh - PX2]);
        const float4 gx = f4diff(Uc[uoffh + 1], Uc[uoffh - 1]);
        float4 hfz, hxq, hyq;
        flux_math4(hc, gz, gy, gx, hfz, hxq, hyq);
        if (isY) sFy[s1][hy_r][hy_c] = hyq;
        else     sFx[s1][hx_r][hx_s] = hxq;
        hm = hc; hc = hp;
    };

    // ============================ prologue ============================
    {
        float4 a, b;
        ld_plane(z0 - 2, a, b); commit(slot4(z0 - 2), a, b); vm = a;
        ld_plane(z0 - 1, a, b); commit(slot4(z0 - 1), a, b); vc = a;
        ld_plane(z0,     a, b); commit(slot4(z0),     a, b);
        const float4 v_z0 = a;
        __syncthreads();

        if (isH) {
            hm = sU[slot4(z0 - 1)][uoffh];
            hc = sU[slot4(z0)][uoffh];
        }

        ld_plane(z0 + 1, pr0, pr1);
        // fill plane z0-1: center only (its y/x comps never read)
        float4 xq_d;
        fill_center(sU[slot4(z0 - 1)], vm, vc, v_z0, fzm, xq_d, 0, false);
        vm = vc; vc = v_z0;
        commit(slot4(z0 + 1), pr0, pr1);   // slot disjoint from live reads
        const float4 vnext1 = pr0;          // v(z0+1)
        __syncthreads();

        ld_plane(z0 + 2, pr0, pr1);
        // fill plane z0: full
        fill_center(sU[slot4(z0)], vm, vc, vnext1, fzc, xq_c, z0 & 1, true);
        if (isH) {
            const float4 hp = sU[slot4(z0 + 1)][uoffh];
            fill_halo(sU[slot4(z0)], hp, z0 & 1);
        }
        vm = vc; vc = vnext1;
    }

    // ============================ main loop ============================
    for (int zi = 0; zi < CHUNK; zi++) {
        const int z = z0 + zi;

        // 1. commit prefetched plane z+2 (slot disjoint from laggard reads)
        commit(slot4(z + 2), pr0, pr1);
        const float4 vnext = pr0;           // v(z+2), own column
        __syncthreads();

        // 2. prefetch plane z+3
        if (zi + 1 < CHUNK) ld_plane(z + 3, pr0, pr1);

        // 3. fill flux plane z+1 (gz from registers; gy/gx from smem+shfl)
        fill_center(sU[slot4(z + 1)], vm, vc, vnext, fzp, xq_n, (z + 1) & 1, true);
        if (isH) {
            const float4 hp = sU[slot4(z + 2)][uoffh];
            fill_halo(sU[slot4(z + 1)], hp, (z + 1) & 1);
        }

        // 4. output plane z
        {
            const int s = z & 1;
            const float4 yp = sFy[s][cfy + 1][tx];
            const float4 ym = sFy[s][cfy - 1][tx];
            float4 xl, xr;
            xl.x = __shfl_up_sync(0xffffffffu, xq_c.x, 1);
            xl.y = __shfl_up_sync(0xffffffffu, xq_c.y, 1);
            xl.z = __shfl_up_sync(0xffffffffu, xq_c.z, 1);
            xl.w = __shfl_up_sync(0xffffffffu, xq_c.w, 1);
            xr.x = __shfl_down_sync(0xffffffffu, xq_c.x, 1);
            xr.y = __shfl_down_sync(0xffffffffu, xq_c.y, 1);
            xr.z = __shfl_down_sync(0xffffffffu, xq_c.z, 1);
            xr.w = __shfl_down_sync(0xffffffffu, xq_c.w, 1);
            if (tx == 0)  xl = sFx[s][ty][0];
            if (tx == 31) xr = sFx[s][ty][1];

            const float mom0 = (fzp.x - fzm.x) + (yp.x - ym.x) + (xr.x - xl.x);
            const float mom1 = (fzp.y - fzm.y) + (yp.y - ym.y) + (xr.y - xl.y);
            const float mom2 = (fzp.z - fzm.z) + (yp.z - ym.z) + (xr.z - xl.z);
            const float en   = (fzp.w - fzm.w) + (yp.w - ym.w) + (xr.w - xl.w);

            const int idx = z * NN2 + gy_ * NN + gx_;
            out[0 * NN3 + idx] = 0.0f;
            out[1 * NN3 + idx] = mom0 * INV2DX;
            out[2 * NN3 + idx] = mom1 * INV2DX;
            out[3 * NN3 + idx] = mom2 * INV2DX;
            out[4 * NN3 + idx] = en * INV2DX;
        }

        // 5. rotate pipelines
        fzm = fzc; fzc = fzp;
        xq_c = xq_n;
        vm = vc; vc = vnext;
    }
}

extern "C" void kernel_launch(void* const* d_in, const int* in_sizes, int n_in,
                              void* d_out, int out_size)
{
    const float* u = (const float*)d_in[0];   // [3, N, N, N]
    const float* T = (const float*)d_in[1];   // [N, N, N]
    float* out = (float*)d_out;               // [5, N, N, N]

    dim3 grid(NN / TX, NN / TY, NN / CHUNK);  // 6 x 24 x 3 = 432 blocks
    dim3 block(TX, TY, 1);
    fused8<<<grid, block>>>(u, T, out);
}